// round 5
// baseline (speedup 1.0000x reference)
#include <cuda_runtime.h>
#include <cstdint>

// Problem constants (from reference setup)
#define B_   32
#define S_   512
#define D_   256
#define TT   128          // frames per block tile
#define EPSF 1e-6f
#define INV_SQRT_2PI 0.3989422804014327f

// shared layout (floats), 3072 + 512 + small
// fast path:  wq[TT*8] packed weights at [0,1024) ; params at [1024,1064)
// fallback:   fc[512) fis[512) fcf[512) fid[512) wf[512)  => [0,2560)
// both:       sdur at [2560, 3072)
#define SMEM_F 3072
#define SDUR_OFF 2560

// dtype-agnostic integer load (inputs may be int32 or int64 depending on jax x64)
__device__ __forceinline__ long long load_i(const void* p, int idx, bool is64) {
    return is64 ? ((const long long*)p)[idx] : (long long)((const int*)p)[idx];
}

// ---- phase 2: each thread owns 4 consecutive d and TT/4 frames ----
// wq is t-major [TT][KP], already normalized and invalid-frame-zeroed.
template<int KP>
__device__ __forceinline__ void phase2v(const float* __restrict__ wq,
                                        const float* __restrict__ embed,
                                        const int*   __restrict__ s_id,
                                        int K,
                                        float* __restrict__ out_tile, // out + (b*T+t0)*D
                                        int tf, int d4, int frames_in_tile)
{
    float4 ev[KP];
    #pragma unroll
    for (int s = 0; s < KP; s++) {
        if (s < K)
            ev[s] = *reinterpret_cast<const float4*>(embed + (size_t)s_id[s] * D_ + d4);
        else
            ev[s] = make_float4(0.f, 0.f, 0.f, 0.f);
    }

    if (frames_in_tile == TT) {
        #pragma unroll 4
        for (int i = 0; i < TT / 4; i++) {
            int t = tf + 4 * i;
            float wv[KP];
            *reinterpret_cast<float4*>(wv) = *reinterpret_cast<const float4*>(wq + t * KP);
            if (KP == 8)
                *reinterpret_cast<float4*>(wv + 4) =
                    *reinterpret_cast<const float4*>(wq + t * KP + 4);
            float4 acc = make_float4(0.f, 0.f, 0.f, 0.f);
            #pragma unroll
            for (int s = 0; s < KP; s++) {
                acc.x = fmaf(wv[s], ev[s].x, acc.x);
                acc.y = fmaf(wv[s], ev[s].y, acc.y);
                acc.z = fmaf(wv[s], ev[s].z, acc.z);
                acc.w = fmaf(wv[s], ev[s].w, acc.w);
            }
            *reinterpret_cast<float4*>(out_tile + (size_t)t * D_ + d4) = acc;
        }
    } else {
        for (int t = tf; t < frames_in_tile; t += 4) {
            float wv[KP];
            *reinterpret_cast<float4*>(wv) = *reinterpret_cast<const float4*>(wq + t * KP);
            if (KP == 8)
                *reinterpret_cast<float4*>(wv + 4) =
                    *reinterpret_cast<const float4*>(wq + t * KP + 4);
            float4 acc = make_float4(0.f, 0.f, 0.f, 0.f);
            #pragma unroll
            for (int s = 0; s < KP; s++) {
                acc.x = fmaf(wv[s], ev[s].x, acc.x);
                acc.y = fmaf(wv[s], ev[s].y, acc.y);
                acc.z = fmaf(wv[s], ev[s].z, acc.z);
                acc.w = fmaf(wv[s], ev[s].w, acc.w);
            }
            *reinterpret_cast<float4*>(out_tile + (size_t)t * D_ + d4) = acc;
        }
    }
}

// ---------------- single fused kernel ----------------
__global__ __launch_bounds__(256)
void gauss_fused_kernel(const void* __restrict__ text,
                        const void* __restrict__ durs,
                        const float* __restrict__ embed,
                        float* __restrict__ out, int T)
{
    __shared__ __align__(16) float smem[SMEM_F];
    __shared__ int sK, stot;

    float* sdur = smem + SDUR_OFF;

    const int b   = blockIdx.y;
    const int t0  = blockIdx.x * TT;
    const int tid = threadIdx.x;
    if (t0 >= T) return;

    // dtype detection: text values are all in [1,256); if int64 (LE), the
    // second 32-bit word is the high half of text[0] == 0; if int32 it's
    // text[0][1] >= 1.
    const bool is64 = (((const int*)text)[1] == 0);

    // ---- load durations, find K (nonzero durs form a prefix) ----
    if (tid == 0) sK = S_;
    __syncthreads();
    for (int s = tid; s < S_; s += 256) {
        long long dv = load_i(durs, b * S_ + s, is64);
        sdur[s] = (float)dv;
        if (dv == 0) atomicMin(&sK, s);
    }
    __syncthreads();
    const int K = sK;

    if (K <= 8) {
        float* wq   = smem;             // [TT][KP]
        float* s_c  = smem + 1024;      // [8]
        float* s_is = s_c + 8;
        float* s_cf = s_is + 8;
        int*   s_id = (int*)(s_cf + 8);

        // ---- serial param scan over the tiny prefix (from shared) ----
        if (tid == 0) {
            float cum = 0.0f;
            for (int k = 0; k < K; k++) {
                float df  = sdur[k];
                float sig = 0.5f * df + EPSF;
                s_c [k] = 0.5f * df + cum;
                s_is[k] = 1.0f / sig;
                s_cf[k] = INV_SQRT_2PI / sig;
                cum += df;
            }
            stot = (int)cum;
        }
        if (tid < K) s_id[tid] = (int)load_i(text, b * S_ + tid, is64);
        __syncthreads();

        const int KP = (K <= 4) ? 4 : 8;

        // ---- phase 1: gaussian weights, t-major packed [t][KP] ----
        const int items = TT * KP;
        for (int idx = tid; idx < items; idx += 256) {
            int t, s;
            if (KP == 4) { t = idx >> 2; s = idx & 3; }
            else         { t = idx >> 3; s = idx & 7; }
            float w = 0.0f;
            if (s < K) {
                float tt = (float)(t0 + t) + 0.5f;
                float z  = (tt - s_c[s]) * s_is[s];
                w = s_cf[s] * __expf(-0.5f * z * z);
            }
            wq[idx] = w;
        }
        __syncthreads();

        // ---- normalize + invalidate per frame, in place ----
        if (tid < TT) {
            float* row = wq + tid * KP;
            float4 w0 = *reinterpret_cast<const float4*>(row);
            float den = EPSF + w0.x + w0.y + w0.z + w0.w;
            float4 w1;
            if (KP == 8) {
                w1 = *reinterpret_cast<const float4*>(row + 4);
                den += w1.x + w1.y + w1.z + w1.w;
            }
            float r = 1.0f / den;
            if (t0 + tid >= stot) r = 0.0f;   // time_invalid frames -> zeros
            w0.x *= r; w0.y *= r; w0.z *= r; w0.w *= r;
            *reinterpret_cast<float4*>(row) = w0;
            if (KP == 8) {
                w1.x *= r; w1.y *= r; w1.z *= r; w1.w *= r;
                *reinterpret_cast<float4*>(row + 4) = w1;
            }
        }
        __syncthreads();

        // ---- phase 2 ----
        const int d4 = (tid & 63) << 2;   // 4 consecutive d per thread
        const int tf = tid >> 6;          // frame phase 0..3
        float* out_tile = out + ((size_t)b * T + t0) * D_;
        int frames = T - t0; if (frames > TT) frames = TT;
        if (KP == 4)
            phase2v<4>(wq, embed, s_id, K, out_tile, tf, d4, frames);
        else
            phase2v<8>(wq, embed, s_id, K, out_tile, tf, d4, frames);
    } else {
        // ---- general fallback (K > 8): slow but correct for any K <= S_ ----
        float* fc  = smem;             // [S_]
        float* fis = smem + S_;        // [S_]
        float* fcf = smem + 2 * S_;    // [S_]
        int*   fid = (int*)(smem + 3 * S_); // [S_]
        float* wf  = smem + 4 * S_;    // [S_]

        if (tid == 0) {
            float cum = 0.0f;
            for (int k = 0; k < K; k++) {
                float df  = sdur[k];
                float sig = 0.5f * df + EPSF;
                fc [k] = 0.5f * df + cum;
                fis[k] = 1.0f / sig;
                fcf[k] = INV_SQRT_2PI / sig;
                cum += df;
            }
            stot = (int)cum;
        }
        for (int k = tid; k < K; k += 256)
            fid[k] = (int)load_i(text, b * S_ + k, is64);
        __syncthreads();
        const int total = stot;

        const int d = tid;
        for (int t = 0; t < TT; t++) {
            int tabs = t0 + t;
            if (tabs >= T) break;
            for (int s = tid; s < K; s += 256) {
                float tt = (float)tabs + 0.5f;
                float z  = (tt - fc[s]) * fis[s];
                wf[s] = fcf[s] * __expf(-0.5f * z * z);
            }
            __syncthreads();
            float den = EPSF;
            for (int s = 0; s < K; s++) den += wf[s];
            float acc = 0.f;
            for (int s = 0; s < K; s++) acc += wf[s] * embed[fid[s] * D_ + d];
            out[((size_t)b * T + tabs) * D_ + d] = (tabs < total) ? acc / den : 0.0f;
            __syncthreads();
        }
    }
}

// ---------------- launcher: ONE kernel node ----------------
extern "C" void kernel_launch(void* const* d_in, const int* in_sizes, int n_in,
                              void* d_out, int out_size)
{
    const void*  text  = d_in[0];                 // int32 or int64, detected on-device
    const void*  durs  = d_in[1];
    const float* embed = (const float*)d_in[2];
    float*       out   = (float*)d_out;

    int T = out_size / (B_ * D_);                 // derive T from output size

    dim3 grid((T + TT - 1) / TT, B_);
    gauss_fused_kernel<<<grid, 256>>>(text, durs, embed, out, T);
}